// round 11
// baseline (speedup 1.0000x reference)
#include <cuda_runtime.h>
#include <math.h>
#include <stdint.h>

#define BSZ 256        // batch B
#define NSEQ 4096      // K*B
#define H 64
#define G4 256
#define ZXD 320
#define LSTM_IN 322
#define TT 50

__device__ __forceinline__ float tanhg(float x) {
    float y;
    asm("tanh.approx.f32 %0, %1;" : "=f"(y) : "f"(x));
    return y;
}
__device__ __forceinline__ float sigg(float x) {
    return fmaf(0.5f, tanhg(0.5f * x), 0.5f);
}
__device__ __forceinline__ uint32_t f2tf(float x) {
    uint32_t r;
    asm("cvt.rna.tf32.f32 %0, %1;" : "=r"(r) : "f"(x));
    return r;
}

// m16n8k8 tf32 mma, D += A*B (D=C in place)
__device__ __forceinline__ void mma8(float* d, const uint4& a,
                                     uint32_t b0, uint32_t b1) {
    asm volatile(
        "mma.sync.aligned.m16n8k8.row.col.f32.tf32.tf32.f32 "
        "{%0,%1,%2,%3}, {%4,%5,%6,%7}, {%8,%9}, {%0,%1,%2,%3};"
        : "+f"(d[0]), "+f"(d[1]), "+f"(d[2]), "+f"(d[3])
        : "r"(a.x), "r"(a.y), "r"(a.z), "r"(a.w), "r"(b0), "r"(b1));
}

// scratch
__device__ float g_G0[NSEQ * G4];   // [n][u*4 + q]
__device__ float g_h0[NSEQ * H];
__device__ float g_c0[NSEQ * H];

// ---------------------------------------------------------------------------
// Phase 1 (unchanged):  [G0 | h0 | c0] = zx @ [Wih[:, :320] | Wh0 | Wc0]^T
// ---------------------------------------------------------------------------
__global__ __launch_bounds__(256) void phase1_kernel(
    const float* __restrict__ x, const float* __restrict__ z,
    const float* __restrict__ Wih, const float* __restrict__ Wh0,
    const float* __restrict__ Wc0,
    const float* __restrict__ bih, const float* __restrict__ bhh,
    const float* __restrict__ bh0, const float* __restrict__ bc0)
{
    __shared__ float As[16][68];
    __shared__ float Ws[16][68];
    const int tid = threadIdx.x;
    const int n0 = blockIdx.x * 64;
    const int c0 = blockIdx.y * 64;
    const int tx = tid & 15, ty = tid >> 4;
    float acc[4][4] = {};

    for (int kt = 0; kt < ZXD; kt += 16) {
        #pragma unroll
        for (int i = 0; i < 4; i++) {
            int e = tid + i * 256;
            int kk = e & 15, rr = e >> 4;
            int n = n0 + rr, m = kt + kk;
            float v = (m < H) ? z[n * H + m]
                              : x[(n & (BSZ - 1)) * 256 + (m - H)];
            As[kk][rr] = v;
        }
        #pragma unroll
        for (int i = 0; i < 4; i++) {
            int e = tid + i * 256;
            int kk = e & 15, cc = e >> 4;
            int j = c0 + cc, m = kt + kk;
            float v;
            if (j < G4)          v = Wih[j * LSTM_IN + m];
            else if (j < G4 + H) v = Wh0[(j - G4) * ZXD + m];
            else                 v = Wc0[(j - G4 - H) * ZXD + m];
            Ws[kk][cc] = v;
        }
        __syncthreads();
        #pragma unroll
        for (int kk = 0; kk < 16; kk++) {
            float a[4], b[4];
            #pragma unroll
            for (int i = 0; i < 4; i++) a[i] = As[kk][ty * 4 + i];
            #pragma unroll
            for (int j = 0; j < 4; j++) b[j] = Ws[kk][tx * 4 + j];
            #pragma unroll
            for (int i = 0; i < 4; i++)
                #pragma unroll
                for (int j = 0; j < 4; j++)
                    acc[i][j] += a[i] * b[j];
        }
        __syncthreads();
    }

    #pragma unroll
    for (int i = 0; i < 4; i++) {
        int n = n0 + ty * 4 + i;
        #pragma unroll
        for (int j = 0; j < 4; j++) {
            int col = c0 + tx * 4 + j;
            float v = acc[i][j];
            if (col < G4) {
                int u = col & 63, q = col >> 6;
                g_G0[n * G4 + u * 4 + q] = v + bih[col] + bhh[col];
            }
            else if (col < G4 + H) g_h0[n * H + (col - G4)]     = v + bh0[col - G4];
            else                   g_c0[n * H + (col - G4 - H)] = v + bc0[col - G4 - H];
        }
    }
}

// ---------------------------------------------------------------------------
// Phase 2: mma.sync tf32 recurrence, merged-MMA pipeline.
// 128 blocks x 32 seqs x 256 threads.
// Iteration i:
//   [1] MMA burst: gates(i) (3-term tf32) AND heads(i-1), both from A=h_{i-1}
//   [2] GMM+LSE for step i-2 (hides mma tail latency)
//   [3] pointwise LSTM -> h_i
//   [4] barrier; write A=h_i (hi/lo), d-cols (row i-1), DT ring, Po; barrier
// 2 barriers per iteration (was 3); loop i = 1..TT+2 with predicates.
// ---------------------------------------------------------------------------
#define SM_BG   0                       // 32nt*9kt*32*4 = 36864 f (hi0,hi1,lo0,lo1)
#define SM_BHD  36864                   // 12nt*9kt*32*2 = 6912 f
#define SM_AH   43776                   // 9kt*2mt*32*4 = 2304 f
#define SM_AL   46080                   // 2304 f
#define SM_PO   48384                   // 32*100 = 3200 f
#define SM_DT   51584                   // [2][32][2] = 128 f
#define SM_TOT  51712
#define SMEM_BYTES (SM_TOT * 4)
#define NTH 256

__global__ __launch_bounds__(NTH, 1) void phase2_kernel(
    const float* __restrict__ inp_seqs, const float* __restrict__ pred_seqs,
    const float* __restrict__ Whh, const float* __restrict__ Wih,
    const float* __restrict__ Wpi, const float* __restrict__ bpi,
    const float* __restrict__ Wmu, const float* __restrict__ bmu,
    const float* __restrict__ Wls, const float* __restrict__ bls,
    const float* __restrict__ Wcorr, const float* __restrict__ bcorr,
    float* __restrict__ out)
{
    extern __shared__ float sm[];
    uint32_t* smu = (uint32_t*)sm;
    const int tid  = threadIdx.x;
    const int lane = tid & 31;
    const int warp = tid >> 5;        // 0..7
    const int nb   = blockIdx.x * 32;
    const int m4   = lane & 3;        // frag col group
    const int sr   = lane >> 2;       // frag row base

    // ---- zero A fragment region ----
    for (int e = tid; e < 4608; e += NTH) sm[SM_AH + e] = 0.f;

    // ---- stage B gates (hi+lo, fragment-major, permuted cols) ----
    for (int e = tid; e < 256 * 72; e += NTH) {
        int j = e / 72, k = e % 72;
        int w = j >> 5, i = (j >> 3) & 3, m = (j >> 1) & 3, b = j & 1;
        int u = 8 * w + 2 * m + (i >> 1);
        int q = 2 * (i & 1) + b;
        int row = q * 64 + u;
        float v = 0.f;
        if (k < 64)       v = Whh[row * 64 + k];
        else if (k == 64) v = Wih[row * LSTM_IN + 320];
        else if (k == 65) v = Wih[row * LSTM_IN + 321];
        uint32_t hi = f2tf(v);
        uint32_t lo = f2tf(v - __uint_as_float(hi));
        int nt = j >> 3, kt = k >> 3, kl = k & 7;
        int lanep = (j & 7) * 4 + (kl & 3);
        int r = kl >> 2;
        uint32_t* bp = smu + SM_BG + ((nt * 9 + kt) * 32 + lanep) * 4;
        bp[r] = hi;
        bp[2 + r] = lo;
    }
    // ---- stage B heads (single tf32) ----
    for (int e = tid; e < 96 * 72; e += NTH) {
        int jj = e / 72, k = e % 72;
        float v = 0.f;
        if (k < 64) {
            if (jj < 16)      v = Wpi[jj * 64 + k];
            else if (jj < 48) v = Wmu[(jj - 16) * 64 + k];
            else if (jj < 80) v = Wls[(jj - 48) * 64 + k];
            else              v = Wcorr[(jj - 80) * 64 + k];
        } else if (k == 66) {
            if (jj < 16)      v = bpi[jj];
            else if (jj < 48) v = bmu[jj - 16];
            else if (jj < 80) v = bls[jj - 48];
            else              v = bcorr[jj - 80];
        }
        int nt = jj >> 3, kt = k >> 3, kl = k & 7;
        int lanep = (jj & 7) * 4 + (kl & 3);
        int r = kl >> 2;
        smu[SM_BHD + ((nt * 9 + kt) * 32 + lanep) * 2 + r] = f2tf(v);
    }
    __syncthreads();   // A zero done before A staging writes below

    // ---- stage A: h0 (hi+lo) ----
    for (int e = tid; e < 32 * 64; e += NTH) {
        int s = e >> 6, k = e & 63;
        float v = g_h0[(nb + s) * 64 + k];
        uint32_t hi = f2tf(v);
        uint32_t lo = f2tf(v - __uint_as_float(hi));
        int kt = k >> 3, mt = s >> 4;
        int lanep = (s & 7) * 4 + (k & 3);
        int r = ((s >> 3) & 1) + 2 * ((k >> 2) & 1);
        int fi = ((kt * 2 + mt) * 32 + lanep) * 4 + r;
        smu[SM_AH + fi] = hi;
        smu[SM_AL + fi] = lo;
    }
    // ---- stage A: d0 = tgt_present, const 1 ----
    if (tid < 32) {
        int s = tid;
        int b = (nb + s) & (BSZ - 1);
        float dx = inp_seqs[(b * 8 + 7) * 24 + 20];
        float dy = inp_seqs[(b * 8 + 7) * 24 + 21];
        int mt = s >> 4, rh = (s >> 3) & 1;
        int base = ((16 + mt) * 32 + (s & 7) * 4);
        uint32_t hx = f2tf(dx), hy = f2tf(dy);
        smu[SM_AH + (base + 0) * 4 + rh] = hx;
        smu[SM_AL + (base + 0) * 4 + rh] = f2tf(dx - __uint_as_float(hx));
        smu[SM_AH + (base + 1) * 4 + rh] = hy;
        smu[SM_AL + (base + 1) * 4 + rh] = f2tf(dy - __uint_as_float(hy));
        smu[SM_AH + (base + 2) * 4 + rh] = f2tf(1.0f);   // col 66 (bias lane)
    }

    // ---- register state: G0 + c for 4 seqs x 2 units ----
    float G0r[4][2][4];
    float c[4][2];
    #pragma unroll
    for (int j = 0; j < 4; j++) {
        int s = sr + (j & 1) * 8 + (j >> 1) * 16;
        int n = nb + s;
        #pragma unroll
        for (int dl = 0; dl < 2; dl++) {
            int u = 8 * warp + 2 * m4 + dl;
            float4 g0 = *(const float4*)(g_G0 + n * 256 + u * 4);
            G0r[j][dl][0] = g0.x; G0r[j][dl][1] = g0.y;
            G0r[j][dl][2] = g0.z; G0r[j][dl][3] = g0.w;
            c[j][dl] = g_c0[n * 64 + u];
        }
    }

    const int b_mine = (nb + lane) & (BSZ - 1);
    const int sh = lane >> 4;
    const int gc = lane & 15;
    float lacc[2] = {0.f, 0.f};

    const uint4* ahp = (const uint4*)(sm + SM_AH) + lane;
    const uint4* alp = (const uint4*)(sm + SM_AL) + lane;
    const uint4* bgp = (const uint4*)(sm + SM_BG) + (4 * warp * 9) * 32 + lane;
    const uint2* bhp = (const uint2*)(sm + SM_BHD) + (2 * warp * 9) * 32 + lane;

    __syncthreads();

    for (int i = 1; i <= TT + 2; i++) {
        // prefetch pred row i-1 (decode for step i+1 AND GMM target for step i)
        float pdx = 0.f, pdy = 0.f;
        if (tid < 32 && i <= TT) {
            const float* pr = pred_seqs + (b_mine * TT + (i - 1)) * 24 + 20;
            pdx = pr[0];
            pdy = pr[1];
        }
        const bool hd_act = (warp < 6) && (i >= 2) && (i <= TT + 1);

        // ======== [1] merged MMA burst: gates(i) + heads(i-1), A = h_{i-1} ====
        float acc[4][2][4];
        float facc[2][2][4];
        if (hd_act) {
            #pragma unroll
            for (int a = 0; a < 2; a++)
                #pragma unroll
                for (int b = 0; b < 2; b++)
                    #pragma unroll
                    for (int r = 0; r < 4; r++) facc[a][b][r] = 0.f;
        }
        if (i <= TT) {
            #pragma unroll
            for (int a = 0; a < 4; a++)
                #pragma unroll
                for (int b = 0; b < 2; b++)
                    #pragma unroll
                    for (int r = 0; r < 4; r++) acc[a][b][r] = 0.f;
            #pragma unroll
            for (int kt = 0; kt < 9; kt++) {
                uint4 ah0 = ahp[(kt * 2 + 0) * 32];
                uint4 ah1 = ahp[(kt * 2 + 1) * 32];
                uint4 al0 = alp[(kt * 2 + 0) * 32];
                uint4 al1 = alp[(kt * 2 + 1) * 32];
                #pragma unroll
                for (int ntl = 0; ntl < 4; ntl++) {
                    uint4 B4 = bgp[(ntl * 9 + kt) * 32];
                    mma8(acc[ntl][0], ah0, B4.x, B4.y);
                    mma8(acc[ntl][1], ah1, B4.x, B4.y);
                    mma8(acc[ntl][0], ah0, B4.z, B4.w);
                    mma8(acc[ntl][1], ah1, B4.z, B4.w);
                    mma8(acc[ntl][0], al0, B4.x, B4.y);
                    mma8(acc[ntl][1], al1, B4.x, B4.y);
                }
                if (hd_act) {
                    uint2 Bh0 = bhp[(0 * 9 + kt) * 32];
                    uint2 Bh1 = bhp[(1 * 9 + kt) * 32];
                    mma8(facc[0][0], ah0, Bh0.x, Bh0.y);
                    mma8(facc[0][1], ah1, Bh0.x, Bh0.y);
                    mma8(facc[1][0], ah0, Bh1.x, Bh1.y);
                    mma8(facc[1][1], ah1, Bh1.x, Bh1.y);
                }
            }
        } else if (hd_act) {   // i == TT+1: heads only
            #pragma unroll
            for (int kt = 0; kt < 9; kt++) {
                uint4 ah0 = ahp[(kt * 2 + 0) * 32];
                uint4 ah1 = ahp[(kt * 2 + 1) * 32];
                uint2 Bh0 = bhp[(0 * 9 + kt) * 32];
                uint2 Bh1 = bhp[(1 * 9 + kt) * 32];
                mma8(facc[0][0], ah0, Bh0.x, Bh0.y);
                mma8(facc[0][1], ah1, Bh0.x, Bh0.y);
                mma8(facc[1][0], ah0, Bh1.x, Bh1.y);
                mma8(facc[1][1], ah1, Bh1.x, Bh1.y);
            }
        }

        // ======== [2] GMM + LSE for step i-2 (hides mma tail latency) ========
        if (i >= 3) {
            #pragma unroll
            for (int it = 0; it < 2; it++) {
                int gs = 4 * warp + 2 * it + sh;
                float txv = sm[SM_DT + (i & 1) * 64 + gs * 2];
                float tyv = sm[SM_DT + (i & 1) * 64 + gs * 2 + 1];
                const float* pr = sm + SM_PO + gs * 100;
                float pi  = pr[gc];
                float2 mu  = *(const float2*)(pr + 16 + 2 * gc);
                float2 lsv = *(const float2*)(pr + 48 + 2 * gc);
                float corr = tanhg(pr[80 + gc]);
                float ls0 = fminf(fmaxf(lsv.x, -10.f), 10.f);
                float ls1 = fminf(fmaxf(lsv.y, -10.f), 10.f);
                float dx = txv - mu.x, dy = tyv - mu.y;
                float z0 = dx * __expf(-ls0);
                float z1 = dy * __expf(-ls1);
                float omr  = 1.f - corr * corr;
                float quad = z0 * z0 + z1 * z1 - 2.f * corr * z0 * z1;
                float cv = -1.8378770664093453f - (ls0 + ls1)
                           - 0.5f * __logf(omr) - 0.5f * __fdividef(quad, omr);
                float a = pi + cv;
                float b2 = pi;
                float ma = a, mb = b2;
                #pragma unroll
                for (int xm = 1; xm < 16; xm <<= 1) {
                    ma = fmaxf(ma, __shfl_xor_sync(0xFFFFFFFFu, ma, xm));
                    mb = fmaxf(mb, __shfl_xor_sync(0xFFFFFFFFu, mb, xm));
                }
                float ea = __expf(a - ma);
                float eb = __expf(b2 - mb);
                #pragma unroll
                for (int xm = 1; xm < 16; xm <<= 1) {
                    ea += __shfl_xor_sync(0xFFFFFFFFu, ea, xm);
                    eb += __shfl_xor_sync(0xFFFFFFFFu, eb, xm);
                }
                float lp = (ma + __logf(ea)) - (mb + __logf(eb));
                lacc[it] += fminf(lp, 50.f);
            }
        }

        // ======== [3] pointwise LSTM (registers) ========
        float hreg[4][2];
        if (i <= TT) {
            #pragma unroll
            for (int j = 0; j < 4; j++) {
                int mt = j >> 1, rh = j & 1;
                #pragma unroll
                for (int dl = 0; dl < 2; dl++) {
                    float gi = acc[2 * dl][mt][2 * rh + 0] + G0r[j][dl][0];
                    float gf = acc[2 * dl][mt][2 * rh + 1] + G0r[j][dl][1];
                    float gg = acc[2 * dl + 1][mt][2 * rh + 0] + G0r[j][dl][2];
                    float go = acc[2 * dl + 1][mt][2 * rh + 1] + G0r[j][dl][3];
                    float cc = sigg(gf) * c[j][dl] + sigg(gi) * tanhg(gg);
                    c[j][dl] = cc;
                    hreg[j][dl] = sigg(go) * tanhg(cc);
                }
            }
        }
        __syncthreads();   // all A/Po/DT reads done

        // ======== [4] writes: A=h_i (hi+lo), d-cols, DT ring, Po ========
        if (i <= TT) {
            #pragma unroll
            for (int j = 0; j < 4; j++) {
                int mt = j >> 1;
                int s = sr + (j & 1) * 8 + mt * 16;
                #pragma unroll
                for (int dl = 0; dl < 2; dl++) {
                    int u = 8 * warp + 2 * m4 + dl;
                    int kt = u >> 3;
                    int lanep = (s & 7) * 4 + (u & 3);
                    int r = ((s >> 3) & 1) + 2 * ((u >> 2) & 1);
                    int fi = ((kt * 2 + mt) * 32 + lanep) * 4 + r;
                    float h = hreg[j][dl];
                    uint32_t hi = f2tf(h);
                    smu[SM_AH + fi] = hi;
                    smu[SM_AL + fi] = f2tf(h - __uint_as_float(hi));
                }
            }
            if (tid < 32) {
                int s = lane;
                sm[SM_DT + (i & 1) * 64 + s * 2]     = pdx;
                sm[SM_DT + (i & 1) * 64 + s * 2 + 1] = pdy;
                int mt = s >> 4, rh = (s >> 3) & 1;
                int base = ((16 + mt) * 32 + (s & 7) * 4);
                uint32_t hx = f2tf(pdx), hy = f2tf(pdy);
                smu[SM_AH + (base + 0) * 4 + rh] = hx;
                smu[SM_AL + (base + 0) * 4 + rh] = f2tf(pdx - __uint_as_float(hx));
                smu[SM_AH + (base + 1) * 4 + rh] = hy;
                smu[SM_AL + (base + 1) * 4 + rh] = f2tf(pdy - __uint_as_float(hy));
            }
        }
        if (hd_act) {
            #pragma unroll
            for (int ntl = 0; ntl < 2; ntl++) {
                int jc = 16 * warp + 8 * ntl + 2 * m4;
                #pragma unroll
                for (int mt = 0; mt < 2; mt++) {
                    int r0 = sr + 16 * mt;
                    *(float2*)(sm + SM_PO + r0 * 100 + jc) =
                        make_float2(facc[ntl][mt][0], facc[ntl][mt][1]);
                    *(float2*)(sm + SM_PO + (r0 + 8) * 100 + jc) =
                        make_float2(facc[ntl][mt][2], facc[ntl][mt][3]);
                }
            }
        }
        __syncthreads();   // new A / Po / DT visible
    }

    if ((lane & 15) == 0) {
        out[nb + 4 * warp + 0 + sh] = lacc[0];
        out[nb + 4 * warp + 2 + sh] = lacc[1];
    }
}

// ---------------------------------------------------------------------------
extern "C" void kernel_launch(void* const* d_in, const int* in_sizes, int n_in,
                              void* d_out, int out_size)
{
    const float* x      = (const float*)d_in[0];
    const float* z      = (const float*)d_in[1];
    const float* inps   = (const float*)d_in[2];
    const float* preds  = (const float*)d_in[3];
    const float* Wh0    = (const float*)d_in[4];
    const float* bh0    = (const float*)d_in[5];
    const float* Wc0    = (const float*)d_in[6];
    const float* bc0    = (const float*)d_in[7];
    const float* Wih    = (const float*)d_in[8];
    const float* Whh    = (const float*)d_in[9];
    const float* bih    = (const float*)d_in[10];
    const float* bhh    = (const float*)d_in[11];
    const float* Wpi    = (const float*)d_in[12];
    const float* bpi    = (const float*)d_in[13];
    const float* Wmu    = (const float*)d_in[14];
    const float* bmu    = (const float*)d_in[15];
    const float* Wls    = (const float*)d_in[16];
    const float* bls    = (const float*)d_in[17];
    const float* Wcorr  = (const float*)d_in[18];
    const float* bcorr  = (const float*)d_in[19];
    float* out = (float*)d_out;

    cudaFuncSetAttribute(phase2_kernel,
                         cudaFuncAttributeMaxDynamicSharedMemorySize, SMEM_BYTES);

    dim3 g1(NSEQ / 64, 384 / 64);
    phase1_kernel<<<g1, 256>>>(x, z, Wih, Wh0, Wc0, bih, bhh, bh0, bc0);

    phase2_kernel<<<NSEQ / 32, NTH, SMEM_BYTES>>>(
        inps, preds, Whh, Wih,
        Wpi, bpi, Wmu, bmu, Wls, bls, Wcorr, bcorr, out);
}